// round 4
// baseline (speedup 1.0000x reference)
#include <cuda_runtime.h>

// Problem constants (fixed by reference_code)
#define T_GRID   8          // occupancy grid 8x8x8 = 512
#define SUBB     7
#define CH       28
#define JC       (SUBB*CH)  // 196
#define NT       5          // region tiles [0,5) per dim (slice 8..72, t_start=0)
#define S0       8
#define QPT      8          // quads per thread
// output: (7,1,28,64,64,64) = 51,380,224 floats = 12,845,056 float4 quads
// tiles quads total: 154*196*1024 = 30,908,416 < 2^31 -> int addressing OK

// Build the 125-entry tile map (tile index or -1) in SMEM from occupancy.
// Warp 0 builds a 512-bit mask; dtype (u8 vs i32) auto-detected via popcount.
__device__ __forceinline__ void build_map(const unsigned char* __restrict__ occ,
                                          int n_occ, unsigned* s_mask, int* s_map)
{
    const int t = threadIdx.x;
    if (t < 32) {
        const int lane = t;
        uint4 v = ((const uint4*)occ)[lane];        // byte view: 16 B per lane
        unsigned w[4] = {v.x, v.y, v.z, v.w};
        unsigned m16 = 0;
        #pragma unroll
        for (int i = 0; i < 4; i++)
            #pragma unroll
            for (int j = 0; j < 4; j++)
                m16 |= (unsigned)(((w[i] >> (8*j)) & 0xffu) != 0) << (i*4 + j);
        int cnt = __popc(m16);
        #pragma unroll
        for (int o = 16; o > 0; o >>= 1) cnt += __shfl_xor_sync(0xffffffffu, cnt, o);
        if (cnt != n_occ) {                          // int32 layout fallback
            const int4* q = (const int4*)occ;
            m16 = 0;
            #pragma unroll
            for (int i = 0; i < 4; i++) {
                int4 ww = q[lane*4 + i];
                m16 |= (unsigned)(ww.x != 0) << (4*i)
                     | (unsigned)(ww.y != 0) << (4*i + 1)
                     | (unsigned)(ww.z != 0) << (4*i + 2)
                     | (unsigned)(ww.w != 0) << (4*i + 3);
            }
        }
        unsigned other = __shfl_xor_sync(0xffffffffu, m16, 1);
        if ((lane & 1) == 0) s_mask[lane >> 1] = (m16 & 0xffffu) | (other << 16);
    }
    __syncthreads();
    if (t < NT*NT*NT) {
        int tz = t % NT, r = t / NT;
        int ty = r % NT, tx = r / NT;
        int lin = (tx * T_GRID + ty) * T_GRID + tz;
        int wq = lin >> 5, bit = lin & 31;
        int pre = 0;
        for (int w = 0; w < wq; w++) pre += __popc(s_mask[w]);
        pre += __popc(s_mask[wq] & ((1u << bit) - 1u));
        s_map[t] = ((s_mask[wq] >> bit) & 1) ? pre : -1;
    }
    __syncthreads();
}

// Fused gather with streaming cache policy on both sides.
// quad id bits: [0:4)=z-quad, [4:10)=y, [10:16)=x, [16:..)=jc
__global__ void __launch_bounds__(256)
gather_fused(const float4* __restrict__ tiles, float4* __restrict__ out,
             const unsigned char* __restrict__ occ, int n_occ)
{
    __shared__ unsigned s_mask[16];
    __shared__ int s_map[NT*NT*NT];
    build_map(occ, n_occ, s_mask, s_map);

    const int total = gridDim.x * 256;
    const int base  = blockIdx.x * 256 + threadIdx.x;

    int src[QPT];   // source quad index, or <0 if zero-fill
    #pragma unroll
    for (int k = 0; k < QPT; k++) {
        int q  = base + k * total;
        int zq = q & 15;
        int t1 = q >> 4;
        int y  = t1 & 63;
        int t2 = t1 >> 6;
        int x  = t2 & 63;
        int jc = t2 >> 6;

        int gx = x + S0, gy = y + S0, gz = zq * 4 + S0;
        int tx = gx >> 4, ty = gy >> 4, tz = gz >> 4;
        int lx = gx & 15, ly = gy & 15, lz = gz & 15;

        int tm = s_map[(tx * NT + ty) * NT + tz];
        int qoff = (lx * 16 + ly) * 4 + (lz >> 2);          // quad within tile
        src[k] = (tm >= 0) ? (((tm * JC + jc) << 10) | qoff) : -1;
    }

    float4 v[QPT];
    #pragma unroll
    for (int k = 0; k < QPT; k++) {
        v[k] = make_float4(0.f, 0.f, 0.f, 0.f);
        if (src[k] >= 0) v[k] = __ldcs(&tiles[src[k]]);     // streaming read
    }

    #pragma unroll
    for (int k = 0; k < QPT; k++)
        __stcs(&out[base + k * total], v[k]);               // streaming write
}

// Guarded 1-quad/thread tail (not launched for this shape; kept for safety).
__global__ void __launch_bounds__(256)
gather_tail(const float4* __restrict__ tiles, float4* __restrict__ out,
            const unsigned char* __restrict__ occ, int n_occ,
            int start, int nquads)
{
    __shared__ unsigned s_mask[16];
    __shared__ int s_map[NT*NT*NT];
    build_map(occ, n_occ, s_mask, s_map);

    int q = start + blockIdx.x * 256 + threadIdx.x;
    if (q >= nquads) return;
    int zq = q & 15;
    int t1 = q >> 4;
    int y  = t1 & 63;
    int t2 = t1 >> 6;
    int x  = t2 & 63;
    int jc = t2 >> 6;
    int gx = x + S0, gy = y + S0, gz = zq * 4 + S0;
    int tm = s_map[((gx >> 4) * NT + (gy >> 4)) * NT + (gz >> 4)];
    float4 v = make_float4(0.f, 0.f, 0.f, 0.f);
    if (tm >= 0)
        v = __ldcs(&tiles[((tm * JC + jc) << 10)
                          | (((gx & 15) * 16 + (gy & 15)) * 4 + ((gz & 15) >> 2))]);
    __stcs(&out[q], v);
}

extern "C" void kernel_launch(void* const* d_in, const int* in_sizes, int n_in,
                              void* d_out, int out_size)
{
    const float*         tiles = (const float*)d_in[0];
    const unsigned char* occ   = (const unsigned char*)d_in[1];

    int n_occ  = in_sizes[0] / (JC * 4096);
    int nquads = out_size / 4;                       // 12,845,056

    int per_block = 256 * QPT;                       // 2048
    int nblocks   = nquads / per_block;              // 6272 (exact)
    int covered   = nblocks * per_block;

    if (nblocks > 0)
        gather_fused<<<nblocks, 256>>>((const float4*)tiles, (float4*)d_out, occ, n_occ);

    if (covered < nquads) {
        int rem = nquads - covered;
        gather_tail<<<(rem + 255) / 256, 256>>>((const float4*)tiles, (float4*)d_out,
                                                occ, n_occ, covered, nquads);
    }
}

// round 5
// speedup vs baseline: 1.0359x; 1.0359x over previous
#include <cuda_runtime.h>

// Problem constants (fixed by reference_code)
#define T_GRID   8          // occupancy grid 8x8x8 = 512
#define SUBB     7
#define CH       28
#define JC       (SUBB*CH)  // 196
#define NT       5          // region tiles [0,5) per dim (slice 8..72, t_start=0)
#define S0       8
#define KJC      7          // jc values per thread
// output: (7,1,28,64,64,64) = 51,380,224 floats = 12,845,056 float4 quads
// source quads: 154*196*1024 = 30,908,416 < 2^31 -> int indexing OK

// Build the 125-entry tile map (tile index or -1) in SMEM from occupancy.
// Warp 0 builds a 512-bit mask; dtype (u8 vs i32) auto-detected via popcount.
__device__ __forceinline__ void build_map(const unsigned char* __restrict__ occ,
                                          int n_occ, unsigned* s_mask, int* s_map)
{
    const int t = threadIdx.x;
    if (t < 32) {
        const int lane = t;
        uint4 v = ((const uint4*)occ)[lane];        // byte view: 16 B per lane
        unsigned w[4] = {v.x, v.y, v.z, v.w};
        unsigned m16 = 0;
        #pragma unroll
        for (int i = 0; i < 4; i++)
            #pragma unroll
            for (int j = 0; j < 4; j++)
                m16 |= (unsigned)(((w[i] >> (8*j)) & 0xffu) != 0) << (i*4 + j);
        int cnt = __popc(m16);
        #pragma unroll
        for (int o = 16; o > 0; o >>= 1) cnt += __shfl_xor_sync(0xffffffffu, cnt, o);
        if (cnt != n_occ) {                          // int32 layout fallback
            const int4* q = (const int4*)occ;
            m16 = 0;
            #pragma unroll
            for (int i = 0; i < 4; i++) {
                int4 ww = q[lane*4 + i];
                m16 |= (unsigned)(ww.x != 0) << (4*i)
                     | (unsigned)(ww.y != 0) << (4*i + 1)
                     | (unsigned)(ww.z != 0) << (4*i + 2)
                     | (unsigned)(ww.w != 0) << (4*i + 3);
            }
        }
        unsigned other = __shfl_xor_sync(0xffffffffu, m16, 1);
        if ((lane & 1) == 0) s_mask[lane >> 1] = (m16 & 0xffffu) | (other << 16);
    }
    __syncthreads();
    if (t < NT*NT*NT) {
        int tz = t % NT, r = t / NT;
        int ty = r % NT, tx = r / NT;
        int lin = (tx * T_GRID + ty) * T_GRID + tz;
        int wq = lin >> 5, bit = lin & 31;
        int pre = 0;
        for (int w = 0; w < wq; w++) pre += __popc(s_mask[w]);
        pre += __popc(s_mask[wq] & ((1u << bit) - 1u));
        s_map[t] = ((s_mask[wq] >> bit) & 1) ? pre : -1;
    }
    __syncthreads();
}

// Each thread owns one spatial site (x, y, zq) and a (j, c0) pair, then copies
// KJC=7 quads at jc = j*28 + c0*7 + k, k=0..6. Source and destination strides
// over k are compile-time constants small enough for LDG/STG immediate offsets:
//   src stride = 1024 quads (16 KB), out stride = 65536 quads (1 MB).
// tid bits: [0:4)=zq, [4:10)=y, [10:16)=x, [16:18)=c0, [18:21)=j
__global__ void __launch_bounds__(256)
gather_fused(const float4* __restrict__ tiles, float4* __restrict__ out,
             const unsigned char* __restrict__ occ, int n_occ)
{
    __shared__ unsigned s_mask[16];
    __shared__ int s_map[NT*NT*NT];
    build_map(occ, n_occ, s_mask, s_map);

    const int tid = blockIdx.x * 256 + threadIdx.x;   // 0 .. 1,835,007

    int zq = tid & 15;
    int y  = (tid >> 4) & 63;
    int x  = (tid >> 10) & 63;
    int c0 = (tid >> 16) & 3;
    int j  = tid >> 18;                               // 0..6

    int gx = x + S0, gy = y + S0, gz = zq * 4 + S0;
    int tx = gx >> 4, ty = gy >> 4, tz = gz >> 4;
    int lx = gx & 15, ly = gy & 15, lz = gz & 15;

    int tm = s_map[(tx * NT + ty) * NT + tz];
    int qoff = (lx * 16 + ly) * 4 + (lz >> 2);        // quad within tile

    int jc0 = j * CH + c0 * KJC;                      // base jc for this thread

    const float4* srcp = tiles + (((tm * JC + jc0) << 10) | qoff);
    float4*       dstp = out   + ((jc0 << 16) | (x << 10) | (y << 4) | zq);

    float4 v[KJC];
    #pragma unroll
    for (int k = 0; k < KJC; k++) {
        v[k] = make_float4(0.f, 0.f, 0.f, 0.f);
        if (tm >= 0) v[k] = srcp[k << 10];            // +k*16KB, immediate offset
    }

    #pragma unroll
    for (int k = 0; k < KJC; k++)
        dstp[k << 16] = v[k];                         // +k*1MB, immediate offset
}

extern "C" void kernel_launch(void* const* d_in, const int* in_sizes, int n_in,
                              void* d_out, int out_size)
{
    const float*         tiles = (const float*)d_in[0];
    const unsigned char* occ   = (const unsigned char*)d_in[1];

    int n_occ    = in_sizes[0] / (JC * 4096);
    int nquads   = out_size / 4;                      // 12,845,056
    int nthreads = nquads / KJC;                      // 1,835,008 (exact)
    int nblocks  = nthreads / 256;                    // 7168 (exact)

    gather_fused<<<nblocks, 256>>>((const float4*)tiles, (float4*)d_out, occ, n_occ);
}